// round 8
// baseline (speedup 1.0000x reference)
#include <cuda_runtime.h>
#include <cstdint>
#include <cstddef>

// Shapes (fixed by the problem)
#define L_DIM   2
#define BAT     32
#define A_DIM   64
#define B_DIM   1024
#define D_DIM   128
#define NBITS   1024

// Packed sign codes: 32 uint32 words per row (1024 bits)
__device__ unsigned g_codes_q[L_DIM * BAT * A_DIM * (NBITS / 32)];
__device__ unsigned g_codes_d[L_DIM * BAT * B_DIM * (NBITS / 32)];

// tf32 hi/lo split arrays, fragment-permuted: [row][ks(16)][t(4)][4 words]
//   word0 = hi(k=ks*8+t), word1 = hi(k+4), word2 = lo(k), word3 = lo(k+4)
__device__ uint32_t g_split_q[(size_t)4096 * 256];
__device__ uint32_t g_split_d[(size_t)65536 * 256];
__device__ uint32_t g_split_r[(size_t)1024 * 256];

// ---------------------------------------------------------------------------
__device__ __forceinline__ uint32_t smem_u32(const void* p) {
    uint32_t a;
    asm("{ .reg .u64 t; cvta.to.shared.u64 t, %1; cvt.u32.u64 %0, t; }"
        : "=r"(a) : "l"(p));
    return a;
}
__device__ __forceinline__ void cpa16(uint32_t saddr, const void* g) {
    asm volatile("cp.async.ca.shared.global [%0], [%1], 16;"
                 :: "r"(saddr), "l"(g) : "memory");
}
#define CP_COMMIT() asm volatile("cp.async.commit_group;" ::: "memory")
#define CP_WAIT1()  asm volatile("cp.async.wait_group 1;" ::: "memory")
#define CP_WAIT0()  asm volatile("cp.async.wait_group 0;" ::: "memory")

__device__ __forceinline__ void mma_tf32(float c[4],
                                         uint32_t a0, uint32_t a1, uint32_t a2, uint32_t a3,
                                         uint32_t b0, uint32_t b1) {
    asm volatile("mma.sync.aligned.m16n8k8.row.col.f32.tf32.tf32.f32 "
                 "{%0,%1,%2,%3}, {%4,%5,%6,%7}, {%8,%9}, {%0,%1,%2,%3};"
                 : "+f"(c[0]), "+f"(c[1]), "+f"(c[2]), "+f"(c[3])
                 : "r"(a0), "r"(a1), "r"(a2), "r"(a3), "r"(b0), "r"(b1));
}

// ---------------------------------------------------------------------------
// Pre-split: fp32 -> (tf32 hi, tf32 lo) in fragment-permuted layout.
// ---------------------------------------------------------------------------
__global__ void split_kernel(const float* __restrict__ src,
                             uint32_t* __restrict__ dst, int total)
{
    int idx = blockIdx.x * blockDim.x + threadIdx.x;
    if (idx >= total) return;
    int row = idx >> 4, ks = idx & 15;
    const float4* p = (const float4*)(src + (size_t)row * D_DIM + ks * 8);
    float4 v0 = p[0], v1 = p[1];
    float f[8] = {v0.x, v0.y, v0.z, v0.w, v1.x, v1.y, v1.z, v1.w};
    uint32_t hi[8], lo[8];
#pragma unroll
    for (int j = 0; j < 8; j++) {
        asm("cvt.rna.tf32.f32 %0, %1;" : "=r"(hi[j]) : "f"(f[j]));
        float l = f[j] - __uint_as_float(hi[j]);
        asm("cvt.rna.tf32.f32 %0, %1;" : "=r"(lo[j]) : "f"(l));
    }
    uint4* o = (uint4*)(dst + (size_t)row * 256 + ks * 16);
#pragma unroll
    for (int t = 0; t < 4; t++)
        o[t] = make_uint4(hi[t], hi[t + 4], lo[t], lo[t + 4]);
}

// ---------------------------------------------------------------------------
// tf32 3-term split GEMM + sign-pack epilogue (legacy mma.sync path).
// CTA tile 128x128; B (R slice) resident in smem; A k32 chunks double-buffered.
// 512 threads = 16 warps in a 4x4 grid, warp tile 32x32 (mf=2, nf=4).
// ---------------------------------------------------------------------------
#define BROWB 1088                 // B smem row stride (bank-conflict free)
#define AROWB 320                  // A smem row stride
#define ABUFB (128 * AROWB)        // 40960 per A buffer
#define SM_A  (128 * BROWB)        // 139264 (B region size)
#define SMEMSZ (SM_A + 2 * ABUFB)  // 221184

__global__ __launch_bounds__(512, 1)
void lsh_mma_kernel(const uint32_t* __restrict__ Asp,
                    const uint32_t* __restrict__ Bsp,
                    unsigned* __restrict__ codes, int m_tiles)
{
    extern __shared__ char smem[];
    const uint32_t sb = smem_u32(smem);
    const int t    = threadIdx.x;
    const int wid  = t >> 5, lane = t & 31;
    const int g    = lane >> 2, tq = lane & 3;
    const int wm   = wid >> 2, wn = wid & 3;     // 4x4 warp grid
    const int n_tile = blockIdx.x;

    // ---- B resident copy: 128 rows x 1KB ----
    {
        const uint32_t* bg = Bsp + (size_t)n_tile * 128 * 256;
#pragma unroll
        for (int i = 0; i < 16; i++) {
            int gi = t + 512 * i, row = gi >> 6, w = gi & 63;
            cpa16(sb + row * BROWB + w * 16, bg + (size_t)row * 256 + w * 4);
        }
        CP_COMMIT();
    }

    auto issueA = [&](int mt, int c, int buf) {
        const uint32_t* ag = Asp + (size_t)mt * 128 * 256 + c * 64;
#pragma unroll
        for (int i = 0; i < 4; i++) {
            int gi = t + 512 * i, row = gi >> 4, w = gi & 15;
            cpa16(sb + SM_A + buf * ABUFB + row * AROWB + w * 16,
                  ag + (size_t)row * 256 + w * 4);
        }
        CP_COMMIT();
    };

    int mt = blockIdx.y;
    if (mt < m_tiles) issueA(mt, 0, 0);

    for (; mt < m_tiles; mt += gridDim.y) {
        float C[2][4][4];
#pragma unroll
        for (int i = 0; i < 2; i++)
#pragma unroll
            for (int j = 0; j < 4; j++)
#pragma unroll
                for (int k = 0; k < 4; k++) C[i][j][k] = 0.0f;

        const int next_mt = mt + gridDim.y;

        for (int c = 0; c < 4; c++) {
            const int buf = c & 1;
            bool more;
            if (c < 3)                  { issueA(mt, c + 1, (c + 1) & 1); more = true; }
            else if (next_mt < m_tiles) { issueA(next_mt, 0, 0);          more = true; }
            else                          more = false;
            if (more) CP_WAIT1(); else CP_WAIT0();
            __syncthreads();

#pragma unroll
            for (int ksc = 0; ksc < 4; ksc++) {
                const int ks = c * 4 + ksc;
                uint4 B4[4], A4[2][2];
#pragma unroll
                for (int nf = 0; nf < 4; nf++) {
                    int n = wn * 32 + nf * 8 + g;
                    B4[nf] = *(const uint4*)(smem + n * BROWB + ks * 64 + tq * 16);
                }
#pragma unroll
                for (int mf = 0; mf < 2; mf++) {
                    int r0 = wm * 32 + mf * 16 + g;
                    const char* base = smem + SM_A + buf * ABUFB + ksc * 64 + tq * 16;
                    A4[mf][0] = *(const uint4*)(base + r0 * AROWB);
                    A4[mf][1] = *(const uint4*)(base + (r0 + 8) * AROWB);
                }
                // term hh: ah x bh  (8 independent accumulator chains)
#pragma unroll
                for (int mf = 0; mf < 2; mf++)
#pragma unroll
                    for (int nf = 0; nf < 4; nf++)
                        mma_tf32(C[mf][nf],
                                 A4[mf][0].x, A4[mf][1].x, A4[mf][0].y, A4[mf][1].y,
                                 B4[nf].x, B4[nf].y);
                // term hl: ah x bl
#pragma unroll
                for (int mf = 0; mf < 2; mf++)
#pragma unroll
                    for (int nf = 0; nf < 4; nf++)
                        mma_tf32(C[mf][nf],
                                 A4[mf][0].x, A4[mf][1].x, A4[mf][0].y, A4[mf][1].y,
                                 B4[nf].z, B4[nf].w);
                // term lh: al x bh
#pragma unroll
                for (int mf = 0; mf < 2; mf++)
#pragma unroll
                    for (int nf = 0; nf < 4; nf++)
                        mma_tf32(C[mf][nf],
                                 A4[mf][0].z, A4[mf][1].z, A4[mf][0].w, A4[mf][1].w,
                                 B4[nf].x, B4[nf].y);
            }
            __syncthreads();
        }

        // ---- epilogue: sign-pack via shfl-OR over the 4 t-lanes ----
        // Warp covers rows wm*32 + mf*16 + {g, g+8}, cols wn*32 + nf*8 + tq*2{,+1}
        // -> exactly one 32-bit code word (word index wn) per row.
#pragma unroll
        for (int mf = 0; mf < 2; mf++) {
            unsigned m0 = 0, m1 = 0;
#pragma unroll
            for (int nf = 0; nf < 4; nf++) {
                int p = nf * 8 + tq * 2;
                m0 |= (C[mf][nf][0] > 0.0f ? 1u : 0u) << p;
                m0 |= (C[mf][nf][1] > 0.0f ? 1u : 0u) << (p + 1);
                m1 |= (C[mf][nf][2] > 0.0f ? 1u : 0u) << p;
                m1 |= (C[mf][nf][3] > 0.0f ? 1u : 0u) << (p + 1);
            }
            m0 |= __shfl_xor_sync(0xffffffffu, m0, 1);
            m0 |= __shfl_xor_sync(0xffffffffu, m0, 2);
            m1 |= __shfl_xor_sync(0xffffffffu, m1, 1);
            m1 |= __shfl_xor_sync(0xffffffffu, m1, 2);
            if (tq == 0) {
                size_t r0 = (size_t)mt * 128 + wm * 32 + mf * 16 + g;
                int wcol = n_tile * 4 + wn;
                codes[r0 * 32 + wcol]       = m0;
                codes[(r0 + 8) * 32 + wcol] = m1;
            }
        }
    }
}

// ---------------------------------------------------------------------------
// popcount Hamming -> cos -> masked output in [BAT,L,A,B] layout. (unchanged)
// ---------------------------------------------------------------------------
__global__ __launch_bounds__(256)
void simmat_kernel(const int* __restrict__ qtok,
                   const int* __restrict__ dtok,
                   float* __restrict__ out)
{
    __shared__ unsigned qw[A_DIM][33];
    __shared__ unsigned dw[64][33];
    __shared__ int s1[A_DIM];
    __shared__ int s2[64];
    __shared__ int qm[A_DIM];
    __shared__ int dm[64];

    const int t  = threadIdx.x;
    const int cc = blockIdx.x;
    const int b  = blockIdx.y;
    const int l  = blockIdx.z;

    const unsigned* qbase = g_codes_q + (size_t)(l * BAT + b) * A_DIM * 32;
    const unsigned* dbase = g_codes_d +
        ((size_t)(l * BAT + b) * B_DIM + (size_t)cc * 64) * 32;

#pragma unroll
    for (int f = t; f < 64 * 32; f += 256) {
        int row = f >> 5, w = f & 31;
        qw[row][w] = qbase[f];
        dw[row][w] = dbase[f];
    }
    if (t < 64)        qm[t]      = qtok[b * A_DIM + t];
    else if (t < 128)  dm[t - 64] = dtok[b * B_DIM + cc * 64 + (t - 64)];
    __syncthreads();

    if (t < 64) {
        int s = 0;
#pragma unroll
        for (int w = 0; w < 32; w++) s += __popc(qw[t][w]);
        s1[t] = s;
    } else if (t < 128) {
        int s = 0;
#pragma unroll
        for (int w = 0; w < 32; w++) s += __popc(dw[t - 64][w]);
        s2[t - 64] = s;
    }
    __syncthreads();

    const int ta = t >> 4;
    const int tc = t & 15;
    int dot[4][4];
#pragma unroll
    for (int ai = 0; ai < 4; ai++)
#pragma unroll
        for (int ci = 0; ci < 4; ci++) dot[ai][ci] = 0;

#pragma unroll
    for (int w = 0; w < 32; w++) {
        unsigned qa[4], dc[4];
#pragma unroll
        for (int ai = 0; ai < 4; ai++) qa[ai] = qw[ta + 16 * ai][w];
#pragma unroll
        for (int ci = 0; ci < 4; ci++) dc[ci] = dw[tc + 16 * ci][w];
#pragma unroll
        for (int ai = 0; ai < 4; ai++)
#pragma unroll
            for (int ci = 0; ci < 4; ci++)
                dot[ai][ci] += __popc(qa[ai] & dc[ci]);
    }

    const float kfac = 3.14159265358979323846f / (float)NBITS;
#pragma unroll
    for (int ai = 0; ai < 4; ai++) {
        int a = ta + 16 * ai;
        bool qz = (qm[a] == 0);
        int  sa = s1[a];
        size_t obase = ((((size_t)b * L_DIM + l) * A_DIM + a) * B_DIM)
                       + (size_t)cc * 64;
#pragma unroll
        for (int ci = 0; ci < 4; ci++) {
            int c   = tc + 16 * ci;
            int ham = sa + s2[c] - 2 * dot[ai][ci];
            float v = (qz || dm[c] == 0) ? 0.0f
                                         : __cosf(kfac * (float)ham);
            out[obase + c] = v;
        }
    }
}

// ---------------------------------------------------------------------------
extern "C" void kernel_launch(void* const* d_in, const int* in_sizes, int n_in,
                              void* d_out, int out_size)
{
    const float* qe = (const float*)d_in[0];
    const float* de = (const float*)d_in[1];
    const int*   qt = (const int*)d_in[2];
    const int*   dt = (const int*)d_in[3];
    const float* r  = (const float*)d_in[4];
    float* out = (float*)d_out;

    unsigned *cq = nullptr, *cd = nullptr;
    uint32_t *sq = nullptr, *sd = nullptr, *sr = nullptr;
    cudaGetSymbolAddress((void**)&cq, g_codes_q);
    cudaGetSymbolAddress((void**)&cd, g_codes_d);
    cudaGetSymbolAddress((void**)&sq, g_split_q);
    cudaGetSymbolAddress((void**)&sd, g_split_d);
    cudaGetSymbolAddress((void**)&sr, g_split_r);

    // Pre-split fp32 -> tf32 hi/lo (fragment-permuted layout)
    split_kernel<<<(4096 * 16 + 255) / 256, 256>>>(qe, sq, 4096 * 16);
    split_kernel<<<(65536 * 16 + 255) / 256, 256>>>(de, sd, 65536 * 16);
    split_kernel<<<(1024 * 16 + 255) / 256, 256>>>(r, sr, 1024 * 16);

    cudaFuncSetAttribute(lsh_mma_kernel,
                         cudaFuncAttributeMaxDynamicSharedMemorySize, SMEMSZ);

    // query: 32 m-tiles; doc: 512 m-tiles. 8 n-slices x 18 persistent rows.
    lsh_mma_kernel<<<dim3(8, 18), 512, SMEMSZ>>>(sq, sr, cq, 32);
    lsh_mma_kernel<<<dim3(8, 18), 512, SMEMSZ>>>(sd, sr, cd, 512);

    simmat_kernel<<<dim3(B_DIM / 64, BAT, L_DIM), 256>>>(qt, dt, out);
}

// round 9
// speedup vs baseline: 2.0091x; 2.0091x over previous
#include <cuda_runtime.h>
#include <cuda_fp16.h>
#include <cstdint>
#include <cstddef>

// Shapes (fixed by the problem)
#define L_DIM   2
#define BAT     32
#define A_DIM   64
#define B_DIM   1024
#define D_DIM   128
#define NBITS   1024

// Packed sign codes: 32 uint32 words per row (1024 bits)
__device__ unsigned g_codes_q[L_DIM * BAT * A_DIM * (NBITS / 32)];
__device__ unsigned g_codes_d[L_DIM * BAT * B_DIM * (NBITS / 32)];

// fp16 hi/lo split arrays, fragment-permuted:
//   per row: [ks(8)][t(4)][4 words] where words = {hi2[t], hi2[t+4], lo2[t], lo2[t+4]}
//   hi2[j] = half2( hi(k=ks*16+2j), hi(k+1) ), same for lo2.  128 words/row.
__device__ uint32_t g_split_q[(size_t)4096 * 128];
__device__ uint32_t g_split_d[(size_t)65536 * 128];
__device__ uint32_t g_split_r[(size_t)1024 * 128];

// ---------------------------------------------------------------------------
__device__ __forceinline__ uint32_t smem_u32(const void* p) {
    uint32_t a;
    asm("{ .reg .u64 t; cvta.to.shared.u64 t, %1; cvt.u32.u64 %0, t; }"
        : "=r"(a) : "l"(p));
    return a;
}
__device__ __forceinline__ void cpa16(uint32_t saddr, const void* g) {
    asm volatile("cp.async.ca.shared.global [%0], [%1], 16;"
                 :: "r"(saddr), "l"(g) : "memory");
}
#define CP_COMMIT() asm volatile("cp.async.commit_group;" ::: "memory")
#define CP_WAIT1()  asm volatile("cp.async.wait_group 1;" ::: "memory")
#define CP_WAIT0()  asm volatile("cp.async.wait_group 0;" ::: "memory")

// m16n8k16 f16 x f16 -> f32
__device__ __forceinline__ void mma_f16(float c[4],
                                        uint32_t a0, uint32_t a1, uint32_t a2, uint32_t a3,
                                        uint32_t b0, uint32_t b1) {
    asm volatile("mma.sync.aligned.m16n8k16.row.col.f32.f16.f16.f32 "
                 "{%0,%1,%2,%3}, {%4,%5,%6,%7}, {%8,%9}, {%0,%1,%2,%3};"
                 : "+f"(c[0]), "+f"(c[1]), "+f"(c[2]), "+f"(c[3])
                 : "r"(a0), "r"(a1), "r"(a2), "r"(a3), "r"(b0), "r"(b1));
}

// ---------------------------------------------------------------------------
// Pre-split: fp32 -> (f16 hi, f16 lo) in fragment-permuted layout.
// One thread per (row, ks): reads 16 contiguous f32, writes 64B contiguous.
// ---------------------------------------------------------------------------
__global__ void split_kernel(const float* __restrict__ src,
                             uint32_t* __restrict__ dst, int total)
{
    int idx = blockIdx.x * blockDim.x + threadIdx.x;
    if (idx >= total) return;
    int row = idx >> 3, ks = idx & 7;
    const float4* p = (const float4*)(src + (size_t)row * D_DIM + ks * 16);
    float f[16];
#pragma unroll
    for (int q = 0; q < 4; q++) {
        float4 v = p[q];
        f[q * 4 + 0] = v.x; f[q * 4 + 1] = v.y;
        f[q * 4 + 2] = v.z; f[q * 4 + 3] = v.w;
    }
    uint32_t hi2[8], lo2[8];
#pragma unroll
    for (int j = 0; j < 8; j++) {
        __half h0 = __float2half_rn(f[2 * j]);
        __half h1 = __float2half_rn(f[2 * j + 1]);
        __half l0 = __float2half_rn(f[2 * j]     - __half2float(h0));
        __half l1 = __float2half_rn(f[2 * j + 1] - __half2float(h1));
        __half2 h = __halves2half2(h0, h1);
        __half2 l = __halves2half2(l0, l1);
        hi2[j] = *(uint32_t*)&h;
        lo2[j] = *(uint32_t*)&l;
    }
    uint4* o = (uint4*)(dst + (size_t)row * 128 + ks * 16);
#pragma unroll
    for (int t = 0; t < 4; t++)
        o[t] = make_uint4(hi2[t], hi2[t + 4], lo2[t], lo2[t + 4]);
}

// ---------------------------------------------------------------------------
// fp16 3-term split GEMM + sign-pack epilogue (m16n8k16 mma.sync).
// CTA tile 128x128; B (R slice) resident in smem; A k32 chunks double-buffered.
// 512 threads = 16 warps in a 4x4 grid, warp tile 32x32 (mf=2, nf=4).
// ---------------------------------------------------------------------------
#define BROWB 576                  // B smem row stride (512B data + 64 pad)
#define AROWB 192                  // A smem row stride (128B data + 64 pad)
#define ABUFB (128 * AROWB)        // 24576 per A buffer
#define SM_A  (128 * BROWB)        // 73728 (B region size)
#define SMEMSZ (SM_A + 2 * ABUFB)  // 122880

__global__ __launch_bounds__(512, 1)
void lsh_mma_kernel(const uint32_t* __restrict__ Asp,
                    const uint32_t* __restrict__ Bsp,
                    unsigned* __restrict__ codes, int m_tiles)
{
    extern __shared__ char smem[];
    const uint32_t sb = smem_u32(smem);
    const int t    = threadIdx.x;
    const int wid  = t >> 5, lane = t & 31;
    const int g    = lane >> 2, tq = lane & 3;
    const int wm   = wid >> 2, wn = wid & 3;     // 4x4 warp grid
    const int n_tile = blockIdx.x;

    // ---- B resident copy: 128 rows x 512B ----
    {
        const uint32_t* bg = Bsp + (size_t)n_tile * 128 * 128;
#pragma unroll
        for (int i = 0; i < 8; i++) {
            int gi = t + 512 * i, row = gi >> 5, w = gi & 31;
            cpa16(sb + row * BROWB + w * 16, bg + (size_t)row * 128 + w * 4);
        }
        CP_COMMIT();
    }

    auto issueA = [&](int mt, int c, int buf) {
        // chunk c = k-steps 2c, 2c+1 -> 32 uint32 per row
        const uint32_t* ag = Asp + (size_t)mt * 128 * 128 + c * 32;
#pragma unroll
        for (int i = 0; i < 2; i++) {
            int gi = t + 512 * i, row = gi >> 3, w = gi & 7;
            cpa16(sb + SM_A + buf * ABUFB + row * AROWB + w * 16,
                  ag + (size_t)row * 128 + w * 4);
        }
        CP_COMMIT();
    };

    int mt = blockIdx.y;
    if (mt < m_tiles) issueA(mt, 0, 0);

    for (; mt < m_tiles; mt += gridDim.y) {
        float C[2][4][4];
#pragma unroll
        for (int i = 0; i < 2; i++)
#pragma unroll
            for (int j = 0; j < 4; j++)
#pragma unroll
                for (int k = 0; k < 4; k++) C[i][j][k] = 0.0f;

        const int next_mt = mt + gridDim.y;

        for (int c = 0; c < 4; c++) {
            const int buf = c & 1;
            bool more;
            if (c < 3)                  { issueA(mt, c + 1, (c + 1) & 1); more = true; }
            else if (next_mt < m_tiles) { issueA(next_mt, 0, 0);          more = true; }
            else                          more = false;
            if (more) CP_WAIT1(); else CP_WAIT0();
            __syncthreads();

#pragma unroll
            for (int ksc = 0; ksc < 2; ksc++) {
                const int ks = c * 2 + ksc;          // global k-step (0..7)
                uint4 B4[4], A4[2][2];
#pragma unroll
                for (int nf = 0; nf < 4; nf++) {
                    int n = wn * 32 + nf * 8 + g;
                    B4[nf] = *(const uint4*)(smem + n * BROWB + ks * 64 + tq * 16);
                }
#pragma unroll
                for (int mf = 0; mf < 2; mf++) {
                    int r0 = wm * 32 + mf * 16 + g;
                    const char* base = smem + SM_A + buf * ABUFB + ksc * 64 + tq * 16;
                    A4[mf][0] = *(const uint4*)(base + r0 * AROWB);
                    A4[mf][1] = *(const uint4*)(base + (r0 + 8) * AROWB);
                }
                // term hh: ah x bh  (8 independent accumulator chains)
#pragma unroll
                for (int mf = 0; mf < 2; mf++)
#pragma unroll
                    for (int nf = 0; nf < 4; nf++)
                        mma_f16(C[mf][nf],
                                A4[mf][0].x, A4[mf][1].x, A4[mf][0].y, A4[mf][1].y,
                                B4[nf].x, B4[nf].y);
                // term hl: ah x bl
#pragma unroll
                for (int mf = 0; mf < 2; mf++)
#pragma unroll
                    for (int nf = 0; nf < 4; nf++)
                        mma_f16(C[mf][nf],
                                A4[mf][0].x, A4[mf][1].x, A4[mf][0].y, A4[mf][1].y,
                                B4[nf].z, B4[nf].w);
                // term lh: al x bh
#pragma unroll
                for (int mf = 0; mf < 2; mf++)
#pragma unroll
                    for (int nf = 0; nf < 4; nf++)
                        mma_f16(C[mf][nf],
                                A4[mf][0].z, A4[mf][1].z, A4[mf][0].w, A4[mf][1].w,
                                B4[nf].x, B4[nf].y);
            }
            __syncthreads();
        }

        // ---- epilogue: sign-pack via shfl-OR over the 4 t-lanes ----
#pragma unroll
        for (int mf = 0; mf < 2; mf++) {
            unsigned m0 = 0, m1 = 0;
#pragma unroll
            for (int nf = 0; nf < 4; nf++) {
                int p = nf * 8 + tq * 2;
                m0 |= (C[mf][nf][0] > 0.0f ? 1u : 0u) << p;
                m0 |= (C[mf][nf][1] > 0.0f ? 1u : 0u) << (p + 1);
                m1 |= (C[mf][nf][2] > 0.0f ? 1u : 0u) << p;
                m1 |= (C[mf][nf][3] > 0.0f ? 1u : 0u) << (p + 1);
            }
            m0 |= __shfl_xor_sync(0xffffffffu, m0, 1);
            m0 |= __shfl_xor_sync(0xffffffffu, m0, 2);
            m1 |= __shfl_xor_sync(0xffffffffu, m1, 1);
            m1 |= __shfl_xor_sync(0xffffffffu, m1, 2);
            if (tq == 0) {
                size_t r0 = (size_t)mt * 128 + wm * 32 + mf * 16 + g;
                int wcol = n_tile * 4 + wn;
                codes[r0 * 32 + wcol]       = m0;
                codes[(r0 + 8) * 32 + wcol] = m1;
            }
        }
    }
}

// ---------------------------------------------------------------------------
// popcount Hamming -> cos -> masked output in [BAT,L,A,B] layout. (unchanged)
// ---------------------------------------------------------------------------
__global__ __launch_bounds__(256)
void simmat_kernel(const int* __restrict__ qtok,
                   const int* __restrict__ dtok,
                   float* __restrict__ out)
{
    __shared__ unsigned qw[A_DIM][33];
    __shared__ unsigned dw[64][33];
    __shared__ int s1[A_DIM];
    __shared__ int s2[64];
    __shared__ int qm[A_DIM];
    __shared__ int dm[64];

    const int t  = threadIdx.x;
    const int cc = blockIdx.x;
    const int b  = blockIdx.y;
    const int l  = blockIdx.z;

    const unsigned* qbase = g_codes_q + (size_t)(l * BAT + b) * A_DIM * 32;
    const unsigned* dbase = g_codes_d +
        ((size_t)(l * BAT + b) * B_DIM + (size_t)cc * 64) * 32;

#pragma unroll
    for (int f = t; f < 64 * 32; f += 256) {
        int row = f >> 5, w = f & 31;
        qw[row][w] = qbase[f];
        dw[row][w] = dbase[f];
    }
    if (t < 64)        qm[t]      = qtok[b * A_DIM + t];
    else if (t < 128)  dm[t - 64] = dtok[b * B_DIM + cc * 64 + (t - 64)];
    __syncthreads();

    if (t < 64) {
        int s = 0;
#pragma unroll
        for (int w = 0; w < 32; w++) s += __popc(qw[t][w]);
        s1[t] = s;
    } else if (t < 128) {
        int s = 0;
#pragma unroll
        for (int w = 0; w < 32; w++) s += __popc(dw[t - 64][w]);
        s2[t - 64] = s;
    }
    __syncthreads();

    const int ta = t >> 4;
    const int tc = t & 15;
    int dot[4][4];
#pragma unroll
    for (int ai = 0; ai < 4; ai++)
#pragma unroll
        for (int ci = 0; ci < 4; ci++) dot[ai][ci] = 0;

#pragma unroll
    for (int w = 0; w < 32; w++) {
        unsigned qa[4], dc[4];
#pragma unroll
        for (int ai = 0; ai < 4; ai++) qa[ai] = qw[ta + 16 * ai][w];
#pragma unroll
        for (int ci = 0; ci < 4; ci++) dc[ci] = dw[tc + 16 * ci][w];
#pragma unroll
        for (int ai = 0; ai < 4; ai++)
#pragma unroll
            for (int ci = 0; ci < 4; ci++)
                dot[ai][ci] += __popc(qa[ai] & dc[ci]);
    }

    const float kfac = 3.14159265358979323846f / (float)NBITS;
#pragma unroll
    for (int ai = 0; ai < 4; ai++) {
        int a = ta + 16 * ai;
        bool qz = (qm[a] == 0);
        int  sa = s1[a];
        size_t obase = ((((size_t)b * L_DIM + l) * A_DIM + a) * B_DIM)
                       + (size_t)cc * 64;
#pragma unroll
        for (int ci = 0; ci < 4; ci++) {
            int c   = tc + 16 * ci;
            int ham = sa + s2[c] - 2 * dot[ai][ci];
            float v = (qz || dm[c] == 0) ? 0.0f
                                         : __cosf(kfac * (float)ham);
            out[obase + c] = v;
        }
    }
}

// ---------------------------------------------------------------------------
extern "C" void kernel_launch(void* const* d_in, const int* in_sizes, int n_in,
                              void* d_out, int out_size)
{
    const float* qe = (const float*)d_in[0];
    const float* de = (const float*)d_in[1];
    const int*   qt = (const int*)d_in[2];
    const int*   dt = (const int*)d_in[3];
    const float* r  = (const float*)d_in[4];
    float* out = (float*)d_out;

    unsigned *cq = nullptr, *cd = nullptr;
    uint32_t *sq = nullptr, *sd = nullptr, *sr = nullptr;
    cudaGetSymbolAddress((void**)&cq, g_codes_q);
    cudaGetSymbolAddress((void**)&cd, g_codes_d);
    cudaGetSymbolAddress((void**)&sq, g_split_q);
    cudaGetSymbolAddress((void**)&sd, g_split_d);
    cudaGetSymbolAddress((void**)&sr, g_split_r);

    // Pre-split fp32 -> f16 hi/lo (fragment-permuted layout); 8 k-steps/row
    split_kernel<<<(4096 * 8 + 255) / 256, 256>>>(qe, sq, 4096 * 8);
    split_kernel<<<(65536 * 8 + 255) / 256, 256>>>(de, sd, 65536 * 8);
    split_kernel<<<(1024 * 8 + 255) / 256, 256>>>(r, sr, 1024 * 8);

    cudaFuncSetAttribute(lsh_mma_kernel,
                         cudaFuncAttributeMaxDynamicSharedMemorySize, SMEMSZ);

    // query: 32 m-tiles; doc: 512 m-tiles. 8 n-slices x 18 persistent rows.
    lsh_mma_kernel<<<dim3(8, 18), 512, SMEMSZ>>>(sq, sr, cq, 32);
    lsh_mma_kernel<<<dim3(8, 18), 512, SMEMSZ>>>(sd, sr, cd, 512);

    simmat_kernel<<<dim3(B_DIM / 64, BAT, L_DIM), 256>>>(qt, dt, out);
}

// round 11
// speedup vs baseline: 2.1338x; 1.0621x over previous
#include <cuda_runtime.h>
#include <cuda_fp16.h>
#include <cstdint>
#include <cstddef>

// Shapes (fixed by the problem)
#define L_DIM   2
#define BAT     32
#define A_DIM   64
#define B_DIM   1024
#define D_DIM   128
#define NBITS   1024

// Packed sign codes: 32 uint32 words per row (1024 bits)
__device__ unsigned g_codes_q[L_DIM * BAT * A_DIM * (NBITS / 32)];
__device__ unsigned g_codes_d[L_DIM * BAT * B_DIM * (NBITS / 32)];

// f16(hi-only) arrays, fragment-permuted. Per row (128 halfs = 64 words):
//   [ksp(4)][tq(4)] uint4 = { ks0:hi2[tq], ks0:hi2[tq+4], ks1:hi2[tq], ks1:hi2[tq+4] }
//   where ks0 = 2*ksp, ks1 = 2*ksp+1 (k16 steps), hi2[j] = half2(k=2j, k=2j+1).
__device__ uint32_t g_half_q[(size_t)4096 * 64];
__device__ uint32_t g_half_d[(size_t)65536 * 64];
__device__ uint32_t g_half_r[(size_t)1024 * 64];

// ---------------------------------------------------------------------------
__device__ __forceinline__ uint32_t smem_u32(const void* p) {
    uint32_t a;
    asm("{ .reg .u64 t; cvta.to.shared.u64 t, %1; cvt.u32.u64 %0, t; }"
        : "=r"(a) : "l"(p));
    return a;
}
__device__ __forceinline__ void cpa16(uint32_t saddr, const void* g) {
    asm volatile("cp.async.ca.shared.global [%0], [%1], 16;"
                 :: "r"(saddr), "l"(g) : "memory");
}
#define CP_COMMIT() asm volatile("cp.async.commit_group;" ::: "memory")
#define CP_WAIT1()  asm volatile("cp.async.wait_group 1;" ::: "memory")
#define CP_WAIT0()  asm volatile("cp.async.wait_group 0;" ::: "memory")

// m16n8k16 f16 x f16 -> f32
__device__ __forceinline__ void mma_f16(float c[4],
                                        uint32_t a0, uint32_t a1, uint32_t a2, uint32_t a3,
                                        uint32_t b0, uint32_t b1) {
    asm volatile("mma.sync.aligned.m16n8k16.row.col.f32.f16.f16.f32 "
                 "{%0,%1,%2,%3}, {%4,%5,%6,%7}, {%8,%9}, {%0,%1,%2,%3};"
                 : "+f"(c[0]), "+f"(c[1]), "+f"(c[2]), "+f"(c[3])
                 : "r"(a0), "r"(a1), "r"(a2), "r"(a3), "r"(b0), "r"(b1));
}

// ---------------------------------------------------------------------------
// Pre-convert: fp32 -> f16 in fragment-permuted layout (hi only).
// One thread per (row, ksp): reads 32 contiguous f32, writes 64B contiguous.
// ---------------------------------------------------------------------------
__global__ void split_kernel(const float* __restrict__ src,
                             uint32_t* __restrict__ dst, int total)
{
    int idx = blockIdx.x * blockDim.x + threadIdx.x;
    if (idx >= total) return;
    int row = idx >> 2, ksp = idx & 3;
    const float4* p = (const float4*)(src + (size_t)row * D_DIM + ksp * 32);
    float f[32];
#pragma unroll
    for (int q = 0; q < 8; q++) {
        float4 v = p[q];
        f[q * 4 + 0] = v.x; f[q * 4 + 1] = v.y;
        f[q * 4 + 2] = v.z; f[q * 4 + 3] = v.w;
    }
    uint32_t h0[8], h1[8];
#pragma unroll
    for (int j = 0; j < 8; j++) {
        __half2 a = __halves2half2(__float2half_rn(f[2 * j]),
                                   __float2half_rn(f[2 * j + 1]));
        __half2 b = __halves2half2(__float2half_rn(f[16 + 2 * j]),
                                   __float2half_rn(f[16 + 2 * j + 1]));
        h0[j] = *(uint32_t*)&a;
        h1[j] = *(uint32_t*)&b;
    }
    uint4* o = (uint4*)(dst + (size_t)row * 64 + ksp * 16);
#pragma unroll
    for (int t = 0; t < 4; t++)
        o[t] = make_uint4(h0[t], h0[t + 4], h1[t], h1[t + 4]);
}

// ---------------------------------------------------------------------------
// hh-only f16 GEMM + sparse exact-fp32 refinement + sign-pack.
// CTA tile 128x128; B (R slice) resident; A full-tile double-buffered.
// 512 threads = 16 warps (4x4 grid), warp tile 32x32.
// ---------------------------------------------------------------------------
#define ROWB  320                   // smem row stride (256B data + 64 pad)
#define TILEB (128 * ROWB)          // 40960
#define SM_A  TILEB                 // A bufs start after B
#define QOFF  (SM_A + 2 * TILEB)    // queue region: count + entries
#define QCAP  3072
#define SMEMSZ (QOFF + 16 + QCAP * 4)

#define TAU 2.5e-3f

__global__ __launch_bounds__(512, 1)
void lsh_hh_kernel(const uint32_t* __restrict__ Ah,
                   const uint32_t* __restrict__ Bh,
                   const float* __restrict__ Af,   // original fp32 rows [M][128]
                   const float* __restrict__ Bf,   // original fp32 R [1024][128]
                   unsigned* __restrict__ codes, int m_tiles)
{
    extern __shared__ char smem[];
    const uint32_t sb = smem_u32(smem);
    const int t    = threadIdx.x;
    const int wid  = t >> 5, lane = t & 31;
    const int g    = lane >> 2, tq = lane & 3;
    const int wm   = wid >> 2, wn = wid & 3;     // 4x4 warp grid
    const int n_tile = blockIdx.x;

    int* qcnt = (int*)(smem + QOFF);
    uint32_t* qbuf = (uint32_t*)(smem + QOFF + 16);
    if (t == 0) *qcnt = 0;

    // ---- B resident copy: 128 rows x 256B ----
    {
        const uint32_t* bg = Bh + (size_t)n_tile * 128 * 64;
#pragma unroll
        for (int i = 0; i < 4; i++) {
            int gi = t + 512 * i, row = gi >> 4, w = gi & 15;
            cpa16(sb + row * ROWB + w * 16, bg + (size_t)row * 64 + w * 4);
        }
        CP_COMMIT();
    }

    auto issueA = [&](int mt, int buf) {
        const uint32_t* ag = Ah + (size_t)mt * 128 * 64;
#pragma unroll
        for (int i = 0; i < 4; i++) {
            int gi = t + 512 * i, row = gi >> 4, w = gi & 15;
            cpa16(sb + SM_A + buf * TILEB + row * ROWB + w * 16,
                  ag + (size_t)row * 64 + w * 4);
        }
        CP_COMMIT();
    };

    int mt = blockIdx.y;
    int buf = 0;
    if (mt < m_tiles) issueA(mt, 0);

    for (; mt < m_tiles; mt += gridDim.y) {
        const int next_mt = mt + gridDim.y;
        if (next_mt < m_tiles) { issueA(next_mt, buf ^ 1); CP_WAIT1(); }
        else                   { CP_WAIT0(); }
        __syncthreads();

        float C[2][4][4];
#pragma unroll
        for (int i = 0; i < 2; i++)
#pragma unroll
            for (int j = 0; j < 4; j++)
#pragma unroll
                for (int k = 0; k < 4; k++) C[i][j][k] = 0.0f;

#pragma unroll
        for (int ksp = 0; ksp < 4; ksp++) {
            uint4 B4[4], A4[2][2];
#pragma unroll
            for (int nf = 0; nf < 4; nf++) {
                int n = wn * 32 + nf * 8 + g;
                B4[nf] = *(const uint4*)(smem + n * ROWB + ksp * 64 + tq * 16);
            }
#pragma unroll
            for (int mf = 0; mf < 2; mf++) {
                int r0 = wm * 32 + mf * 16 + g;
                const char* base = smem + SM_A + buf * TILEB + ksp * 64 + tq * 16;
                A4[mf][0] = *(const uint4*)(base + r0 * ROWB);
                A4[mf][1] = *(const uint4*)(base + (r0 + 8) * ROWB);
            }
            // k16 step ks0 (words .x/.y)
#pragma unroll
            for (int mf = 0; mf < 2; mf++)
#pragma unroll
                for (int nf = 0; nf < 4; nf++)
                    mma_f16(C[mf][nf],
                            A4[mf][0].x, A4[mf][1].x, A4[mf][0].y, A4[mf][1].y,
                            B4[nf].x, B4[nf].y);
            // k16 step ks1 (words .z/.w)
#pragma unroll
            for (int mf = 0; mf < 2; mf++)
#pragma unroll
                for (int nf = 0; nf < 4; nf++)
                    mma_f16(C[mf][nf],
                            A4[mf][0].z, A4[mf][1].z, A4[mf][0].w, A4[mf][1].w,
                            B4[nf].z, B4[nf].w);
        }

        // ---- flag ambiguous dots (|hh| < TAU) into the refinement queue ----
#pragma unroll
        for (int mf = 0; mf < 2; mf++)
#pragma unroll
            for (int nf = 0; nf < 4; nf++)
#pragma unroll
                for (int idx = 0; idx < 4; idx++) {
                    float v = C[mf][nf][idx];
                    if (fabsf(v) < TAU) {
                        int row = mt * 128 + wm * 32 + mf * 16 + g + ((idx >> 1) ? 8 : 0);
                        int col = n_tile * 128 + wn * 32 + nf * 8 + tq * 2 + (idx & 1);
                        int qi = atomicAdd(qcnt, 1);
                        if (qi < QCAP) qbuf[qi] = ((uint32_t)row << 10) | (uint32_t)col;
                    }
                }

        // ---- provisional sign-pack via shfl-OR over the 4 t-lanes ----
#pragma unroll
        for (int mf = 0; mf < 2; mf++) {
            unsigned m0 = 0, m1 = 0;
#pragma unroll
            for (int nf = 0; nf < 4; nf++) {
                int p = nf * 8 + tq * 2;
                m0 |= (C[mf][nf][0] > 0.0f ? 1u : 0u) << p;
                m0 |= (C[mf][nf][1] > 0.0f ? 1u : 0u) << (p + 1);
                m1 |= (C[mf][nf][2] > 0.0f ? 1u : 0u) << p;
                m1 |= (C[mf][nf][3] > 0.0f ? 1u : 0u) << (p + 1);
            }
            m0 |= __shfl_xor_sync(0xffffffffu, m0, 1);
            m0 |= __shfl_xor_sync(0xffffffffu, m0, 2);
            m1 |= __shfl_xor_sync(0xffffffffu, m1, 1);
            m1 |= __shfl_xor_sync(0xffffffffu, m1, 2);
            if (tq == 0) {
                size_t r0 = (size_t)mt * 128 + wm * 32 + mf * 16 + g;
                int wcol = n_tile * 4 + wn;
                codes[r0 * 32 + wcol]       = m0;
                codes[(r0 + 8) * 32 + wcol] = m1;
            }
        }
        __syncthreads();   // A-buffer reuse + queue/codes ordering
        buf ^= 1;
    }

    // ---- refinement: exact fp32 dot for queued elements, patch bits ----
    __threadfence();
    __syncthreads();
    int nq = *qcnt; if (nq > QCAP) nq = QCAP;
    for (int i = t; i < nq; i += 512) {
        uint32_t e = qbuf[i];
        int row = e >> 10, col = e & 1023;
        const float4* pa = (const float4*)(Af + (size_t)row * D_DIM);
        const float4* pb = (const float4*)(Bf + (size_t)col * D_DIM);
        float d = 0.0f;
#pragma unroll 8
        for (int w = 0; w < 32; w++) {
            float4 x = pa[w], y = pb[w];
            d += x.x * y.x + x.y * y.y + x.z * y.z + x.w * y.w;
        }
        unsigned* wp = codes + (size_t)row * 32 + (col >> 5);
        unsigned bit = 1u << (col & 31);
        if (d > 0.0f) atomicOr(wp, bit);
        else          atomicAnd(wp, ~bit);
    }
}

// ---------------------------------------------------------------------------
// popcount Hamming -> cos -> masked output in [BAT,L,A,B] layout. (unchanged)
// ---------------------------------------------------------------------------
__global__ __launch_bounds__(256)
void simmat_kernel(const int* __restrict__ qtok,
                   const int* __restrict__ dtok,
                   float* __restrict__ out)
{
    __shared__ unsigned qw[A_DIM][33];
    __shared__ unsigned dw[64][33];
    __shared__ int s1[A_DIM];
    __shared__ int s2[64];
    __shared__ int qm[A_DIM];
    __shared__ int dm[64];

    const int t  = threadIdx.x;
    const int cc = blockIdx.x;
    const int b  = blockIdx.y;
    const int l  = blockIdx.z;

    const unsigned* qbase = g_codes_q + (size_t)(l * BAT + b) * A_DIM * 32;
    const unsigned* dbase = g_codes_d +
        ((size_t)(l * BAT + b) * B_DIM + (size_t)cc * 64) * 32;

#pragma unroll
    for (int f = t; f < 64 * 32; f += 256) {
        int row = f >> 5, w = f & 31;
        qw[row][w] = qbase[f];
        dw[row][w] = dbase[f];
    }
    if (t < 64)        qm[t]      = qtok[b * A_DIM + t];
    else if (t < 128)  dm[t - 64] = dtok[b * B_DIM + cc * 64 + (t - 64)];
    __syncthreads();

    if (t < 64) {
        int s = 0;
#pragma unroll
        for (int w = 0; w < 32; w++) s += __popc(qw[t][w]);
        s1[t] = s;
    } else if (t < 128) {
        int s = 0;
#pragma unroll
        for (int w = 0; w < 32; w++) s += __popc(dw[t - 64][w]);
        s2[t - 64] = s;
    }
    __syncthreads();

    const int ta = t >> 4;
    const int tc = t & 15;
    int dot[4][4];
#pragma unroll
    for (int ai = 0; ai < 4; ai++)
#pragma unroll
        for (int ci = 0; ci < 4; ci++) dot[ai][ci] = 0;

#pragma unroll
    for (int w = 0; w < 32; w++) {
        unsigned qa[4], dc[4];
#pragma unroll
        for (int ai = 0; ai < 4; ai++) qa[ai] = qw[ta + 16 * ai][w];
#pragma unroll
        for (int ci = 0; ci < 4; ci++) dc[ci] = dw[tc + 16 * ci][w];
#pragma unroll
        for (int ai = 0; ai < 4; ai++)
#pragma unroll
            for (int ci = 0; ci < 4; ci++)
                dot[ai][ci] += __popc(qa[ai] & dc[ci]);
    }

    const float kfac = 3.14159265358979323846f / (float)NBITS;
#pragma unroll
    for (int ai = 0; ai < 4; ai++) {
        int a = ta + 16 * ai;
        bool qz = (qm[a] == 0);
        int  sa = s1[a];
        size_t obase = ((((size_t)b * L_DIM + l) * A_DIM + a) * B_DIM)
                       + (size_t)cc * 64;
#pragma unroll
        for (int ci = 0; ci < 4; ci++) {
            int c   = tc + 16 * ci;
            int ham = sa + s2[c] - 2 * dot[ai][ci];
            float v = (qz || dm[c] == 0) ? 0.0f
                                         : __cosf(kfac * (float)ham);
            out[obase + c] = v;
        }
    }
}

// ---------------------------------------------------------------------------
extern "C" void kernel_launch(void* const* d_in, const int* in_sizes, int n_in,
                              void* d_out, int out_size)
{
    const float* qe = (const float*)d_in[0];
    const float* de = (const float*)d_in[1];
    const int*   qt = (const int*)d_in[2];
    const int*   dt = (const int*)d_in[3];
    const float* r  = (const float*)d_in[4];
    float* out = (float*)d_out;

    unsigned *cq = nullptr, *cd = nullptr;
    uint32_t *hq = nullptr, *hd = nullptr, *hr = nullptr;
    cudaGetSymbolAddress((void**)&cq, g_codes_q);
    cudaGetSymbolAddress((void**)&cd, g_codes_d);
    cudaGetSymbolAddress((void**)&hq, g_half_q);
    cudaGetSymbolAddress((void**)&hd, g_half_d);
    cudaGetSymbolAddress((void**)&hr, g_half_r);

    // fp32 -> f16 (fragment-permuted, hi only); one thread per (row, ksp)
    split_kernel<<<(4096 * 4 + 255) / 256, 256>>>(qe, hq, 4096 * 4);
    split_kernel<<<(65536 * 4 + 255) / 256, 256>>>(de, hd, 65536 * 4);
    split_kernel<<<(1024 * 4 + 255) / 256, 256>>>(r, hr, 1024 * 4);

    cudaFuncSetAttribute(lsh_hh_kernel,
                         cudaFuncAttributeMaxDynamicSharedMemorySize, SMEMSZ);

    // query: 32 m-tiles; doc: 512 m-tiles. 8 n-slices x 18 persistent rows.
    lsh_hh_kernel<<<dim3(8, 18), 512, SMEMSZ>>>(hq, hr, qe, r, cq, 32);
    lsh_hh_kernel<<<dim3(8, 18), 512, SMEMSZ>>>(hd, hr, de, r, cd, 512);

    simmat_kernel<<<dim3(B_DIM / 64, BAT, L_DIM), 256>>>(qt, dt, out);
}